// round 10
// baseline (speedup 1.0000x reference)
#include <cuda_runtime.h>
#include <cstdint>
#include <cstddef>

// STPCell fused kernel, R8: persistent work-list (592 CTAs, unit = (j, 8
// batches), 1.2% tail) with minimal per-unit overhead: px precomputed by a
// tiny separate kernel, static cp.async ring (ND=4, distance 4, compile-time
// stage indices, uniform 1-commit/iter), seamless cross-unit prefetch.

#define HH    1024
#define IND   512
#define BB    32
#define NCTA  592                      // 4 per SM * 148 SMs
#define NUNIT 4096                     // 1024 j * 4 b-groups
#define BPU   8                        // batches per unit
#define ND    4                        // ring stages == prefetch distance
#define BSTR  ((size_t)HH * HH * 4)    // bytes between batches of X/U

__device__ float g_px[HH * BB];        // (p @ x)[j, b]

__device__ __forceinline__ float sigf(float v) {
    return 1.0f / (1.0f + __expf(-v));
}

__device__ __forceinline__ void cp16(uint32_t saddr, const void* gaddr) {
    asm volatile("cp.async.cg.shared.global [%0], [%1], 16;\n"
                 :: "r"(saddr), "l"(gaddr));
}
#define CP_COMMIT() asm volatile("cp.async.commit_group;\n" ::: "memory")
#define CP_WAIT(n)  asm volatile("cp.async.wait_group %0;\n" :: "n"(n) : "memory")

// ---------------------------------------------------------------------------
// px[j,b] = sum_i p[j,i] * x[i,b]
// ---------------------------------------------------------------------------
__global__ __launch_bounds__(256) void px_kernel(
    const float* __restrict__ p,
    const float* __restrict__ x)
{
    int j   = blockIdx.x;
    int tid = threadIdx.x;
    int b   = tid & 31;
    int seg = tid >> 5;

    const float* prow = p + j * IND;
    float acc = 0.0f;
    #pragma unroll 8
    for (int i = seg * 64; i < seg * 64 + 64; ++i)
        acc = fmaf(prow[i], x[i * BB + b], acc);

    __shared__ float red[8][BB];
    red[seg][b] = acc;
    __syncthreads();

    if (tid < BB) {
        float s = 0.0f;
        #pragma unroll
        for (int q = 0; q < 8; ++q) s += red[q][tid];
        g_px[j * BB + tid] = s;
    }
}

// ---------------------------------------------------------------------------
// Main persistent kernel.
// ---------------------------------------------------------------------------
__global__ __launch_bounds__(256, 4) void stp_main(
    const float* __restrict__ h,      // (B, H)
    const float* __restrict__ X,      // (B, H, H)
    const float* __restrict__ U,      // (B, H, H)
    const float* __restrict__ c_x,    // (H, H)
    const float* __restrict__ c_u,    // (H, H)
    const float* __restrict__ c_U,    // (H, H)
    const float* __restrict__ c_h,    // (H, 1)
    const float* __restrict__ w,      // (H, H)
    const float* __restrict__ bias,   // (H, 1)
    float* __restrict__ out)          // (B, H)
{
    const int cta  = blockIdx.x;
    const int tid  = threadIdx.x;
    const int lane = tid & 31;
    const int warp = tid >> 5;
    const size_t toff = (size_t)tid * 16;

    __shared__ float4 xst[ND][256];    // 16 KB
    __shared__ float4 ust[ND][256];    // 16 KB
    __shared__ float  sred[8][BPU];
    __shared__ float  hj_s[BPU];

    const float4* __restrict__ h4 = reinterpret_cast<const float4*>(h);
    const char* Xc = reinterpret_cast<const char*>(X);
    const char* Uc = reinterpret_cast<const char*>(U);
    const uint32_t xs0 = (uint32_t)__cvta_generic_to_shared(&xst[0][tid]);
    const uint32_t us0 = (uint32_t)__cvta_generic_to_shared(&ust[0][tid]);

    const int T = (NUNIT - 1 - cta) / NCTA + 1;   // 6 or 7 units

    int j  = cta >> 2;
    int bb = (cta & 3) * BPU;
    size_t cur = (size_t)bb * BSTR + (size_t)j * 4096 + toff;  // byte base

    // prologue: fill ring with seq 0..3 (batches bb..bb+3)
    #pragma unroll
    for (int s = 0; s < ND; ++s) {
        cp16(xs0 + s * 4096, Xc + cur + (size_t)s * BSTR);
        cp16(us0 + s * 4096, Uc + cur + (size_t)s * BSTR);
        CP_COMMIT();
    }

    // ================= unit loop =================
    #pragma unroll 1
    for (int t = 0; t < T; ++t) {
        // next unit base (last unit: refetch self — harmless, keeps commits uniform)
        int jn = j, bbn = bb;
        if (t + 1 < T) {
            const int un = cta + (t + 1) * NCTA;
            jn  = un >> 2;
            bbn = (un & 3) * BPU;
        }
        const size_t nxt = (size_t)bbn * BSTR + (size_t)jn * 4096 + toff;

        __syncthreads();               // hj_s/sred safe to rewrite

        // per-unit constants (L2-shared with the 3 sibling CTAs of this j)
        const int rowP = j * (HH / 4) + tid;
        const float4 cxv = __ldg(reinterpret_cast<const float4*>(c_x) + rowP);
        const float4 cuv = __ldg(reinterpret_cast<const float4*>(c_u) + rowP);
        const float4 cUv = __ldg(reinterpret_cast<const float4*>(c_U) + rowP);
        const float4 wv  = __ldg(reinterpret_cast<const float4*>(w)   + rowP);

        if (tid < BPU) hj_s[tid] = h[(bb + tid) * HH + j];

        float4 zx, zu, uc;
        zx.x = 0.001f + 0.099f * sigf(cxv.x);
        zx.y = 0.001f + 0.099f * sigf(cxv.y);
        zx.z = 0.001f + 0.099f * sigf(cxv.z);
        zx.w = 0.001f + 0.099f * sigf(cxv.w);
        zu.x = 0.001f + 0.099f * sigf(cuv.x);
        zu.y = 0.001f + 0.099f * sigf(cuv.y);
        zu.z = 0.001f + 0.099f * sigf(cuv.z);
        zu.w = 0.001f + 0.099f * sigf(cuv.w);
        uc.x = 0.9f * sigf(cUv.x);
        uc.y = 0.9f * sigf(cUv.y);
        uc.z = 0.9f * sigf(cUv.z);
        uc.w = 0.9f * sigf(cUv.w);

        __syncthreads();               // hj_s published

        // ---- 8 batches: 2 groups of 4, static ring schedule ----
        #pragma unroll
        for (int g = 0; g < 2; ++g) {
            float a[4] = {0.0f, 0.0f, 0.0f, 0.0f};

            #pragma unroll
            for (int qq = 0; qq < 4; ++qq) {
                const int q = g * 4 + qq;          // compile-time constant

                CP_WAIT(3);                        // seq q complete
                const float4 x0 = xst[q & 3][tid];
                const float4 u0 = ust[q & 3][tid];

                // prefetch seq q+4 into the slot just read
                {
                    const size_t adr = (q < 4)
                        ? cur + (size_t)(q + 4) * BSTR
                        : nxt + (size_t)(q - 4) * BSTR;
                    cp16(xs0 + (q & 3) * 4096, Xc + adr);
                    cp16(us0 + (q & 3) * 4096, Uc + adr);
                    CP_COMMIT();
                }

                const float4 hv = __ldg(h4 + (bb + q) * (HH / 4) + tid);
                const float  hj = hj_s[q];

                // X_new = fma(z_x, 1-X, X) - U*(X*hj)
                // U_new = Ucap*(z_u+hj) + U*((1-z_u)-Ucap*hj), clip [Ucap,1]
                // a[qq] += (w * U_new * X_new) * h[b,k]
                #define STP_PROC(C)                                         \
                {                                                           \
                    float xx = x0.C, uu = u0.C;                             \
                    float xnew = fmaf(zx.C, 1.0f - xx, xx);                 \
                    xnew = fmaf(-uu, xx * hj, xnew);                        \
                    float addu = uc.C * (zu.C + hj);                        \
                    float cofu = fmaf(-uc.C, hj, 1.0f - zu.C);              \
                    float unew = fmaf(uu, cofu, addu);                      \
                    unew = fminf(fmaxf(unew, uc.C), 1.0f);                 \
                    a[qq] = fmaf(wv.C * unew * xnew, hv.C, a[qq]);          \
                }
                STP_PROC(x) STP_PROC(y) STP_PROC(z) STP_PROC(w)
                #undef STP_PROC
            }

            // 4 interleaved shuffle trees
            #pragma unroll
            for (int o = 16; o > 0; o >>= 1) {
                a[0] += __shfl_xor_sync(0xffffffffu, a[0], o);
                a[1] += __shfl_xor_sync(0xffffffffu, a[1], o);
                a[2] += __shfl_xor_sync(0xffffffffu, a[2], o);
                a[3] += __shfl_xor_sync(0xffffffffu, a[3], o);
            }
            if (lane == 0) {
                sred[warp][g * 4 + 0] = a[0];
                sred[warp][g * 4 + 1] = a[1];
                sred[warp][g * 4 + 2] = a[2];
                sred[warp][g * 4 + 3] = a[3];
            }
        }
        __syncthreads();

        // ---- finalize: thread q (< 8) writes out[bb+q, j] ----
        if (tid < BPU) {
            float rec = 0.0f;
            #pragma unroll
            for (int q = 0; q < 8; ++q) rec += sred[q][tid];

            float pre = rec + g_px[j * BB + bb + tid] + __ldg(bias + j);
            float zh  = 0.5f * sigf(__ldg(c_h + j));      // E_H = 0.5
            float hbj = hj_s[tid];                        // == h[b*HH + j]
            out[(bb + tid) * HH + j] = fmaf(zh, sigf(pre) - hbj, hbj);
        }

        j = jn; bb = bbn; cur = nxt;
    }

    CP_WAIT(0);   // drain tail prefetches
}

// ---------------------------------------------------------------------------
// Inputs (metadata order): x, h, X, U, c_x, c_u, c_U, c_h, w, p, b
// ---------------------------------------------------------------------------
extern "C" void kernel_launch(void* const* d_in, const int* in_sizes, int n_in,
                              void* d_out, int out_size)
{
    const float* x_in = (const float*)d_in[0];
    const float* h    = (const float*)d_in[1];
    const float* X    = (const float*)d_in[2];
    const float* U    = (const float*)d_in[3];
    const float* c_x  = (const float*)d_in[4];
    const float* c_u  = (const float*)d_in[5];
    const float* c_U  = (const float*)d_in[6];
    const float* c_h  = (const float*)d_in[7];
    const float* w    = (const float*)d_in[8];
    const float* p    = (const float*)d_in[9];
    const float* bias = (const float*)d_in[10];
    float* out = (float*)d_out;

    px_kernel<<<HH, 256>>>(p, x_in);
    stp_main<<<NCTA, 256>>>(h, X, U, c_x, c_u, c_U, c_h, w, bias, out);
}